// round 1
// baseline (speedup 1.0000x reference)
#include <cuda_runtime.h>

// Problem constants
#define DIM   256          // DIM_IN
#define BATCH 1024         // B
#define NI    32640        // C(256,2)

// Tile config for the quadratic-form kernel
#define TI     64          // i-tile
#define TJ     64          // j-tile
#define RPB    64          // row-pairs per block (128 rows, 2 rows packed per f32x2 lane)
#define XPITCH 66          // padded pitch (float2 units) for x tiles: keeps 16B alignment, breaks bank conflicts

// Symmetrized, halved, lane-duplicated coefficient matrix: A2[i*DIM+j] = {c/2, c/2}
__device__ float2 g_A2[DIM * DIM];

// ---------------------------------------------------------------------------
// Kernel 1: build A2 from weight_inputs, and zero the output buffer.
// out[b] = sum_{i<j} c_ij x_i x_j  with  c_ij = (w0+w1)*w0*w1
//        = sum_{i,j} A[i][j] x_i x_j  with  A = c/2 symmetric, zero diag.
// k(i,j) for i<j (lexicographic combos): k = 255*i - i*(i-1)/2 + (j-i-1)
// ---------------------------------------------------------------------------
__global__ void build_A_kernel(const float* __restrict__ w, float* __restrict__ out) {
    const int i = blockIdx.x;   // 0..255
    const int j = threadIdx.x;  // 0..255

    if (i < BATCH / DIM) out[i * DIM + j] = 0.0f;  // zero all 1024 outputs

    if (j > i) {
        const int k = i * 255 - (i * (i - 1)) / 2 + (j - i - 1);
        const float w0 = w[k];
        const float w1 = w[NI + k];
        const float c = 0.5f * (w0 + w1) * w0 * w1;
        const float2 v = make_float2(c, c);
        g_A2[i * DIM + j] = v;
        g_A2[j * DIM + i] = v;
    } else if (j == i) {
        g_A2[i * DIM + j] = make_float2(0.0f, 0.0f);
    }
}

// Packed f32x2 FMA (Blackwell): d = a*b + c on both lanes, one FMA-pipe slot.
__device__ __forceinline__ float2 fma2(float2 a, float2 b, float2 c) {
    float2 d;
    asm("fma.rn.f32x2 %0, %1, %2, %3;"
        : "=l"(*reinterpret_cast<unsigned long long*>(&d))
        : "l"(*reinterpret_cast<const unsigned long long*>(&a)),
          "l"(*reinterpret_cast<const unsigned long long*>(&b)),
          "l"(*reinterpret_cast<const unsigned long long*>(&c)));
    return d;
}

// ---------------------------------------------------------------------------
// Kernel 2: out[r] += sum_{i in I, j in J} A[i][j] * x[r][i] * x[r][j]
// Grid: (4 i-tiles, 4 j-tiles, 8 row-groups) = 128 blocks (one full wave).
// Block: 256 threads, 128 rows as 64 f32x2 row-pairs, 64x64 (i,j) tile.
// Thread: 4 row-pairs x 4 j columns of the z-accumulator (16 float2 regs).
// Inner step: 4x LDS.128 + 16x fma.rn.f32x2  -> FMA-pipe bound.
// ---------------------------------------------------------------------------
__global__ void __launch_bounds__(256, 1)
quad_kernel(const float* __restrict__ x, float* __restrict__ out) {
    extern __shared__ char smem_raw[];
    float2* xI  = reinterpret_cast<float2*>(smem_raw);  // [TI][XPITCH] f2: x rows packed, i-tile cols
    float2* xJ  = xI + TI * XPITCH;                     // [TJ][XPITCH] f2: j-tile cols
    float2* As  = xJ + TJ * XPITCH;                     // [TI][TJ] f2 (lane-duplicated A)
    float2* red = As;                                   // reduction buffer (reuses As after loop)

    const int t     = threadIdx.x;
    const int ibase = blockIdx.x * TI;
    const int jbase = blockIdx.y * TJ;
    const int rbase = blockIdx.z * (2 * RPB);

    // Load x tiles: xI[c][rp] = {x[r0][ibase+c], x[r0+1][ibase+c]}, coalesced over c.
    for (int idx = t; idx < TI * RPB; idx += 256) {
        const int rp = idx >> 6;
        const int c  = idx & 63;
        const float* xr = x + (rbase + 2 * rp) * DIM;
        xI[c * XPITCH + rp] = make_float2(xr[ibase + c], xr[DIM + ibase + c]);
        xJ[c * XPITCH + rp] = make_float2(xr[jbase + c], xr[DIM + jbase + c]);
    }
    // Load A tile (coalesced).
    for (int idx = t; idx < TI * TJ; idx += 256) {
        As[idx] = g_A2[(ibase + (idx >> 6)) * DIM + jbase + (idx & 63)];
    }
    __syncthreads();

    const int gj  = t & 15;
    const int gr  = t >> 4;
    const int rp0 = gr * 4;
    const int j0  = gj * 4;

    float2 acc[4][4];
#pragma unroll
    for (int a = 0; a < 4; ++a)
#pragma unroll
        for (int b = 0; b < 4; ++b) acc[a][b] = make_float2(0.0f, 0.0f);

    // Main loop: z2[rp][j] += A[i][j] * x2[rp][i]
#pragma unroll 4
    for (int i = 0; i < TI; ++i) {
        const float4 xa = *reinterpret_cast<const float4*>(&xI[i * XPITCH + rp0]);
        const float4 xb = *reinterpret_cast<const float4*>(&xI[i * XPITCH + rp0 + 2]);
        const float4 aa = *reinterpret_cast<const float4*>(&As[i * TJ + j0]);
        const float4 ab = *reinterpret_cast<const float4*>(&As[i * TJ + j0 + 2]);
        float2 xr[4] = { {xa.x, xa.y}, {xa.z, xa.w}, {xb.x, xb.y}, {xb.z, xb.w} };
        float2 ar[4] = { {aa.x, aa.y}, {aa.z, aa.w}, {ab.x, ab.y}, {ab.z, ab.w} };
#pragma unroll
        for (int rr = 0; rr < 4; ++rr)
#pragma unroll
            for (int jj = 0; jj < 4; ++jj)
                acc[rr][jj] = fma2(xr[rr], ar[jj], acc[rr][jj]);
    }
    __syncthreads();  // done reading As; safe to reuse as reduction buffer

    // Epilogue: partial[rp] = sum_j z2[rp][j] * x2[rp][j]
#pragma unroll
    for (int rr = 0; rr < 4; ++rr) {
        const int rpg = rp0 + rr;
        float2 s = make_float2(0.0f, 0.0f);
#pragma unroll
        for (int jj = 0; jj < 4; ++jj)
            s = fma2(acc[rr][jj], xJ[(j0 + jj) * XPITCH + rpg], s);
        red[rpg * 16 + gj] = s;
    }
    __syncthreads();

    // Reduce the 16 j-groups per row-pair, then one atomicAdd per row.
    if (t < RPB) {
        float2 tot = make_float2(0.0f, 0.0f);
#pragma unroll
        for (int g = 0; g < 16; ++g) {
            const float2 v = red[t * 16 + g];
            tot.x += v.x;
            tot.y += v.y;
        }
        atomicAdd(&out[rbase + 2 * t],     tot.x);
        atomicAdd(&out[rbase + 2 * t + 1], tot.y);
    }
}

// ---------------------------------------------------------------------------
// Launch: inputs per metadata order: x [1024,256] f32, weight_inputs [1,2,32640] f32,
// perm_mat [65280] i32 (unused: the combination structure is closed-form).
// ---------------------------------------------------------------------------
extern "C" void kernel_launch(void* const* d_in, const int* in_sizes, int n_in,
                              void* d_out, int out_size) {
    const float* x = (const float*)d_in[0];
    const float* w = (const float*)d_in[1];
    float* out = (float*)d_out;

    const int smem_bytes = (2 * TI * XPITCH + TI * TJ) * (int)sizeof(float2);  // 100352
    cudaFuncSetAttribute(quad_kernel, cudaFuncAttributeMaxDynamicSharedMemorySize, smem_bytes);

    build_A_kernel<<<DIM, DIM>>>(w, out);                 // builds A2, zeroes out
    quad_kernel<<<dim3(4, 4, 8), 256, smem_bytes>>>(x, out);
}

// round 3
// speedup vs baseline: 1.2865x; 1.2865x over previous
#include <cuda_runtime.h>

#define DIM   256     // DIM_IN
#define BATCH 1024    // B
#define NI    32640   // C(256,2)

#define TT     64     // i/j tile size
#define ROWS   32     // batch rows per block
#define XPI    34     // xI pitch (floats): [col][row]
#define XPJ    68     // xJ pitch (floats): [row][col], 272B rows (16B aligned)

// 10 unordered tile pairs (ti <= tj) over 4 tiles of 64 — constant memory (LDCU path)
__constant__ unsigned char cTI[10] = {0,0,0,0,1,1,1,2,2,3};
__constant__ unsigned char cTJ[10] = {0,1,2,3,1,2,3,2,3,3};

__global__ void zero_out_kernel(float* __restrict__ out) {
    out[threadIdx.x] = 0.0f;
}

// Packed f32x2 FMA (one FMA-pipe slot, 2 fp32 FMAs)
__device__ __forceinline__ float2 fma2(float2 a, float2 b, float2 c) {
    float2 d;
    asm("fma.rn.f32x2 %0, %1, %2, %3;"
        : "=l"(*reinterpret_cast<unsigned long long*>(&d))
        : "l"(*reinterpret_cast<const unsigned long long*>(&a)),
          "l"(*reinterpret_cast<const unsigned long long*>(&b)),
          "l"(*reinterpret_cast<const unsigned long long*>(&c)));
    return d;
}

// out[b] = sum_{i<j} (w0+w1)*w0*w1 * x[b,i]*x[b,j]
// Block = one (i-tile, j-tile) unordered pair x 32 batch rows.
// f32x2 lanes = 2 adjacent j columns; A pairs load naturally, x lane-dup is 1 mov.
__global__ void __launch_bounds__(256, 4)
quad_kernel(const float* __restrict__ x, const float* __restrict__ w,
            float* __restrict__ out) {
    __shared__ __align__(16) float As [TT * TT];     // A[i][j] tile (scalar), 16KB
    __shared__ __align__(16) float xIs[TT * XPI];    // [col i][row r], 8.7KB
    __shared__ __align__(16) float xJs[ROWS * XPJ];  // [row r][col j], 8.7KB

    const int t     = threadIdx.x;
    const int pair  = blockIdx.x;
    const int ti    = cTI[pair];
    const int tj    = cTJ[pair];
    const bool diag = (ti == tj);
    const int ibase = ti * TT;
    const int jbase = tj * TT;
    const int rbase = blockIdx.y * ROWS;

    // ---- Prologue: A tile on the fly from w (coalesced: consecutive j -> consecutive k)
    for (int idx = t; idx < TT * TT; idx += 256) {
        const int il = idx >> 6, jl = idx & 63;
        const int gi = ibase + il, gj = jbase + jl;
        float cv = 0.0f;
        if (gi != gj) {
            const int a = min(gi, gj), b = max(gi, gj);
            const int k = a * 255 - (a * (a - 1)) / 2 + (b - a - 1);
            const float w0 = __ldg(&w[k]);
            const float w1 = __ldg(&w[NI + k]);
            cv = (w0 + w1) * w0 * w1;
            if (diag) cv *= 0.5f;   // diag tile sees both (i,j) and (j,i)
        }
        As[idx] = cv;
    }
    // ---- x tiles (global coalesced over columns)
    for (int idx = t; idx < ROWS * TT; idx += 256) {
        const int c = idx & 63, r = idx >> 6;             // 64 cols x 32 rows, 8 iters
        const float xv_i = __ldg(&x[(rbase + r) * DIM + ibase + c]);
        const float xv_j = (ibase == jbase) ? xv_i : __ldg(&x[(rbase + r) * DIM + jbase + c]);
        xIs[c * XPI + r] = xv_i;
        xJs[r * XPJ + c] = xv_j;
    }
    __syncthreads();

    // Thread tile: 2 rows x 4 j  (4 f32x2 accumulators, lanes = j pairs)
    const int gj = t & 15;            // 16 j-groups
    const int j0 = gj * 4;
    const int r0 = (t >> 4) * 2;      // 16 row-groups x 2 rows = 32 rows

    float2 a00 = {0.f,0.f}, a01 = {0.f,0.f}, a10 = {0.f,0.f}, a11 = {0.f,0.f};

#pragma unroll 8
    for (int i = 0; i < TT; ++i) {
        const float2 xr  = *reinterpret_cast<const float2*>(&xIs[i * XPI + r0]); // rows r0,r0+1 (broadcast)
        const float4 av  = *reinterpret_cast<const float4*>(&As [i * TT  + j0]); // A[i][j0..j0+3]
        const float2 A01 = make_float2(av.x, av.y);
        const float2 A23 = make_float2(av.z, av.w);
        const float2 xd0 = make_float2(xr.x, xr.x);
        const float2 xd1 = make_float2(xr.y, xr.y);
        a00 = fma2(xd0, A01, a00);
        a01 = fma2(xd0, A23, a01);
        a10 = fma2(xd1, A01, a10);
        a11 = fma2(xd1, A23, a11);
    }

    // ---- Epilogue: row dot with x_J, shuffle-reduce over the 16 j-groups
    const float4 xj0v = *reinterpret_cast<const float4*>(&xJs[ r0      * XPJ + j0]);
    const float4 xj1v = *reinterpret_cast<const float4*>(&xJs[(r0 + 1) * XPJ + j0]);
    float2 s0 = fma2(a00, make_float2(xj0v.x, xj0v.y),
                fma2(a01, make_float2(xj0v.z, xj0v.w), make_float2(0.f, 0.f)));
    float2 s1 = fma2(a10, make_float2(xj1v.x, xj1v.y),
                fma2(a11, make_float2(xj1v.z, xj1v.w), make_float2(0.f, 0.f)));
    float v0 = s0.x + s0.y;
    float v1 = s1.x + s1.y;

#pragma unroll
    for (int m = 8; m > 0; m >>= 1) {   // reduce within 16-lane group (same row pair)
        v0 += __shfl_xor_sync(0xffffffffu, v0, m, 32);
        v1 += __shfl_xor_sync(0xffffffffu, v1, m, 32);
    }
    if (gj == 0) {
        atomicAdd(&out[rbase + r0],     v0);
        atomicAdd(&out[rbase + r0 + 1], v1);
    }
}

extern "C" void kernel_launch(void* const* d_in, const int* in_sizes, int n_in,
                              void* d_out, int out_size) {
    const float* x = (const float*)d_in[0];
    const float* w = (const float*)d_in[1];
    float* out = (float*)d_out;

    zero_out_kernel<<<1, BATCH>>>(out);
    quad_kernel<<<dim3(10, BATCH / ROWS), 256>>>(x, w, out);  // 320 blocks, one wave
}

// round 4
// speedup vs baseline: 1.6098x; 1.2512x over previous
#include <cuda_runtime.h>

#define DIM   256     // DIM_IN
#define BATCH 1024    // B
#define NI    32640   // C(256,2)

#define TT     64     // i/j tile size
#define ROWS   32     // batch rows per block
#define XPI    34     // xI pitch (floats): [col][row]
#define XPJ    68     // xJ pitch (floats): [row][col], 272B rows (16B aligned)

// 10 unordered tile pairs (ti <= tj) over 4 tiles of 64
__constant__ unsigned char cTI[10] = {0,0,0,0,1,1,1,2,2,3};
__constant__ unsigned char cTJ[10] = {0,1,2,3,1,2,3,2,3,3};

__global__ void zero_out_kernel(float* __restrict__ out) {
    out[threadIdx.x] = 0.0f;
}

// Packed f32x2 FMA (one FMA-pipe slot, 2 fp32 FMAs)
__device__ __forceinline__ float2 fma2(float2 a, float2 b, float2 c) {
    float2 d;
    asm("fma.rn.f32x2 %0, %1, %2, %3;"
        : "=l"(*reinterpret_cast<unsigned long long*>(&d))
        : "l"(*reinterpret_cast<const unsigned long long*>(&a)),
          "l"(*reinterpret_cast<const unsigned long long*>(&b)),
          "l"(*reinterpret_cast<const unsigned long long*>(&c)));
    return d;
}

// out[b] = sum_{i<j} (w0+w1)*w0*w1 * x[b,i]*x[b,j]
// Block = one unordered (i-tile, j-tile) pair x 32 batch rows.
// Diagonal tiles use a STRICTLY UPPER triangular A-tile (full c, zeros below):
// no double counting, and — crucially — every w access has gi<gj, so
// consecutive lanes -> consecutive k -> fully coalesced (no scattered LDG).
__global__ void __launch_bounds__(256, 4)
quad_kernel(const float* __restrict__ x, const float* __restrict__ w,
            float* __restrict__ out) {
    __shared__ __align__(16) float As [TT * TT];     // A tile (scalar), 16KB
    __shared__ __align__(16) float xIs[TT * XPI];    // [col i][row r], 8.7KB
    __shared__ __align__(16) float xJs[ROWS * XPJ];  // [row r][col j], 8.7KB

    const int t     = threadIdx.x;
    const int pair  = blockIdx.x;
    const int ibase = cTI[pair] * TT;
    const int jbase = cTJ[pair] * TT;
    const int rbase = blockIdx.y * ROWS;

    // ---- Prologue: A tile on the fly from w. All loads coalesced (gi<gj only).
#pragma unroll
    for (int step = 0; step < (TT * TT) / 256; ++step) {
        const int idx = step * 256 + t;
        const int il = idx >> 6, jl = idx & 63;
        const int gi = ibase + il, gj = jbase + jl;
        float cv = 0.0f;
        if (gj > gi) {   // always true for off-diag tiles; upper half of diag tiles
            const int k = gi * 255 - (gi * (gi - 1)) / 2 + (gj - gi - 1);
            const float w0 = __ldg(&w[k]);
            const float w1 = __ldg(&w[NI + k]);
            cv = (w0 + w1) * w0 * w1;
        }
        As[idx] = cv;
    }
    // ---- x tiles (global coalesced over columns)
#pragma unroll
    for (int step = 0; step < (ROWS * TT) / 256; ++step) {
        const int idx = step * 256 + t;
        const int c = idx & 63, r = idx >> 6;
        const float xv_i = __ldg(&x[(rbase + r) * DIM + ibase + c]);
        const float xv_j = (ibase == jbase) ? xv_i : __ldg(&x[(rbase + r) * DIM + jbase + c]);
        xIs[c * XPI + r] = xv_i;
        xJs[r * XPJ + c] = xv_j;
    }
    __syncthreads();

    // Thread tile: 2 rows x 4 j  (4 f32x2 accumulators, lanes = j pairs)
    const int gjg = t & 15;           // 16 j-groups
    const int j0  = gjg * 4;
    const int r0  = (t >> 4) * 2;     // 16 row-groups x 2 rows = 32 rows

    float2 a00 = {0.f,0.f}, a01 = {0.f,0.f}, a10 = {0.f,0.f}, a11 = {0.f,0.f};

#pragma unroll 8
    for (int i = 0; i < TT; ++i) {
        const float2 xr  = *reinterpret_cast<const float2*>(&xIs[i * XPI + r0]); // rows r0,r0+1 (broadcast)
        const float4 av  = *reinterpret_cast<const float4*>(&As [i * TT  + j0]); // A[i][j0..j0+3]
        const float2 A01 = make_float2(av.x, av.y);
        const float2 A23 = make_float2(av.z, av.w);
        const float2 xd0 = make_float2(xr.x, xr.x);
        const float2 xd1 = make_float2(xr.y, xr.y);
        a00 = fma2(xd0, A01, a00);
        a01 = fma2(xd0, A23, a01);
        a10 = fma2(xd1, A01, a10);
        a11 = fma2(xd1, A23, a11);
    }

    // ---- Epilogue: row dot with x_J, shuffle-reduce over the 16 j-groups
    const float4 xj0v = *reinterpret_cast<const float4*>(&xJs[ r0      * XPJ + j0]);
    const float4 xj1v = *reinterpret_cast<const float4*>(&xJs[(r0 + 1) * XPJ + j0]);
    float2 s0 = fma2(a00, make_float2(xj0v.x, xj0v.y),
                fma2(a01, make_float2(xj0v.z, xj0v.w), make_float2(0.f, 0.f)));
    float2 s1 = fma2(a10, make_float2(xj1v.x, xj1v.y),
                fma2(a11, make_float2(xj1v.z, xj1v.w), make_float2(0.f, 0.f)));
    float v0 = s0.x + s0.y;
    float v1 = s1.x + s1.y;

#pragma unroll
    for (int m = 8; m > 0; m >>= 1) {   // reduce within 16-lane group (same row pair)
        v0 += __shfl_xor_sync(0xffffffffu, v0, m, 32);
        v1 += __shfl_xor_sync(0xffffffffu, v1, m, 32);
    }
    if (gjg == 0) {
        atomicAdd(&out[rbase + r0],     v0);
        atomicAdd(&out[rbase + r0 + 1], v1);
    }
}

extern "C" void kernel_launch(void* const* d_in, const int* in_sizes, int n_in,
                              void* d_out, int out_size) {
    const float* x = (const float*)d_in[0];
    const float* w = (const float*)d_in[1];
    float* out = (float*)d_out;

    zero_out_kernel<<<1, BATCH>>>(out);
    quad_kernel<<<dim3(10, BATCH / ROWS), 256>>>(x, w, out);  // 320 blocks, one wave
}

// round 5
// speedup vs baseline: 1.7143x; 1.0649x over previous
#include <cuda_runtime.h>

#define DIM   256     // DIM_IN
#define BATCH 1024    // B
#define NI    32640   // C(256,2)

#define TT     32     // i/j tile size (8 tiles)
#define ROWS   64     // batch rows per block
#define NPAIR  36     // C(8,2)+8 unordered tile pairs
#define XPI    68     // xIs pitch in floats over rows (64+4, mult of 4 for float4)
#define XPJ    36     // xJs pitch in floats over cols (32+4, even for float2)

// Unordered tile pairs (ti <= tj) over 8 tiles of 32
__constant__ unsigned char cTI[NPAIR] = {0,0,0,0,0,0,0,0, 1,1,1,1,1,1,1, 2,2,2,2,2,2,
                                         3,3,3,3,3, 4,4,4,4, 5,5,5, 6,6, 7};
__constant__ unsigned char cTJ[NPAIR] = {0,1,2,3,4,5,6,7, 1,2,3,4,5,6,7, 2,3,4,5,6,7,
                                         3,4,5,6,7, 4,5,6,7, 5,6,7, 6,7, 7};

__global__ void zero_out_kernel(float* __restrict__ out) {
    out[threadIdx.x] = 0.0f;
}

// Packed f32x2 FMA (one FMA-pipe slot, 2 fp32 FMAs)
__device__ __forceinline__ float2 fma2(float2 a, float2 b, float2 c) {
    float2 d;
    asm("fma.rn.f32x2 %0, %1, %2, %3;"
        : "=l"(*reinterpret_cast<unsigned long long*>(&d))
        : "l"(*reinterpret_cast<const unsigned long long*>(&a)),
          "l"(*reinterpret_cast<const unsigned long long*>(&b)),
          "l"(*reinterpret_cast<const unsigned long long*>(&c)));
    return d;
}

// out[b] = sum_{i<j} (w0+w1)*w0*w1 * x[b,i]*x[b,j]
// Block = one unordered (i-tile, j-tile) pair x 64 batch rows.
// Diag tiles: strictly-upper A with full c (coalesced w, no double count).
// Thread tile: 4 rows x 2 j (one f32x2 j-pair per row).
__global__ void __launch_bounds__(256, 4)
quad_kernel(const float* __restrict__ x, const float* __restrict__ w,
            float* __restrict__ out) {
    __shared__ __align__(16) float As [TT * TT];     // 4KB
    __shared__ __align__(16) float xIs[TT * XPI];    // [col i][row r], 8.7KB
    __shared__ __align__(16) float xJs[ROWS * XPJ];  // [row r][col j], 9.2KB

    const int t     = threadIdx.x;
    const int pair  = blockIdx.x;
    const int ibase = cTI[pair] * TT;
    const int jbase = cTJ[pair] * TT;
    const int rbase = blockIdx.y * ROWS;
    const bool diag = (ibase == jbase);

    // ---- A tile from w: all loads have gi<gj -> consecutive k -> coalesced.
#pragma unroll
    for (int step = 0; step < (TT * TT) / 256; ++step) {
        const int idx = step * 256 + t;
        const int gi = ibase + (idx >> 5);
        const int gj = jbase + (idx & 31);
        float cv = 0.0f;
        if (gj > gi) {
            const int k = gi * 255 - (gi * (gi - 1)) / 2 + (gj - gi - 1);
            const float w0 = __ldg(&w[k]);
            const float w1 = __ldg(&w[NI + k]);
            cv = (w0 + w1) * w0 * w1;
        }
        As[idx] = cv;
    }
    // ---- x tiles: warp reads 32 consecutive cols of one row (coalesced).
#pragma unroll
    for (int step = 0; step < (ROWS * TT) / 256; ++step) {
        const int idx = step * 256 + t;
        const int c = idx & 31, r = idx >> 5;
        const float xv_i = __ldg(&x[(rbase + r) * DIM + ibase + c]);
        const float xv_j = diag ? xv_i : __ldg(&x[(rbase + r) * DIM + jbase + c]);
        xIs[c * XPI + r] = xv_i;     // transposed store (8-way STS, prologue only)
        xJs[r * XPJ + c] = xv_j;
    }
    __syncthreads();

    const int jg = t & 15;            // 16 j-groups x 2 j = 32 j
    const int j0 = jg * 2;
    const int r0 = (t >> 4) * 4;      // 16 row-groups x 4 rows = 64 rows

    float2 a0 = {0.f,0.f}, a1 = {0.f,0.f}, a2 = {0.f,0.f}, a3 = {0.f,0.f};

#pragma unroll 8
    for (int i = 0; i < TT; ++i) {
        const float4 xr = *reinterpret_cast<const float4*>(&xIs[i * XPI + r0]); // 4 rows
        const float2 av = *reinterpret_cast<const float2*>(&As [i * TT  + j0]); // 2 j
        a0 = fma2(make_float2(xr.x, xr.x), av, a0);
        a1 = fma2(make_float2(xr.y, xr.y), av, a1);
        a2 = fma2(make_float2(xr.z, xr.z), av, a2);
        a3 = fma2(make_float2(xr.w, xr.w), av, a3);
    }

    // ---- Epilogue: dot with x_J per row, shuffle-reduce the 16 j-groups.
    const float2 xj0 = *reinterpret_cast<const float2*>(&xJs[(r0 + 0) * XPJ + j0]);
    const float2 xj1 = *reinterpret_cast<const float2*>(&xJs[(r0 + 1) * XPJ + j0]);
    const float2 xj2 = *reinterpret_cast<const float2*>(&xJs[(r0 + 2) * XPJ + j0]);
    const float2 xj3 = *reinterpret_cast<const float2*>(&xJs[(r0 + 3) * XPJ + j0]);
    float v0 = a0.x * xj0.x + a0.y * xj0.y;
    float v1 = a1.x * xj1.x + a1.y * xj1.y;
    float v2 = a2.x * xj2.x + a2.y * xj2.y;
    float v3 = a3.x * xj3.x + a3.y * xj3.y;

#pragma unroll
    for (int m = 8; m > 0; m >>= 1) {   // reduce within 16-lane j-groups
        v0 += __shfl_xor_sync(0xffffffffu, v0, m, 32);
        v1 += __shfl_xor_sync(0xffffffffu, v1, m, 32);
        v2 += __shfl_xor_sync(0xffffffffu, v2, m, 32);
        v3 += __shfl_xor_sync(0xffffffffu, v3, m, 32);
    }
    if (jg == 0) {
        atomicAdd(&out[rbase + r0 + 0], v0);
        atomicAdd(&out[rbase + r0 + 1], v1);
        atomicAdd(&out[rbase + r0 + 2], v2);
        atomicAdd(&out[rbase + r0 + 3], v3);
    }
}

extern "C" void kernel_launch(void* const* d_in, const int* in_sizes, int n_in,
                              void* d_out, int out_size) {
    const float* x = (const float*)d_in[0];
    const float* w = (const float*)d_in[1];
    float* out = (float*)d_out;

    zero_out_kernel<<<1, BATCH>>>(out);
    quad_kernel<<<dim3(NPAIR, BATCH / ROWS), 256>>>(x, w, out);  // 576 blocks
}

// round 6
// speedup vs baseline: 2.0561x; 1.1994x over previous
#include <cuda_runtime.h>

#define DIM   256     // DIM_IN
#define BATCH 1024    // B
#define NI    32640   // C(256,2)

#define TT     32     // i/j tile size (8 tiles of 32)
#define ROWS   128    // batch rows per block
#define NPAIR  36     // unordered tile pairs
#define XPI    132    // xIs pitch (floats) over rows: 128+4, mult of 4 for float4
#define XPJ    36     // xJs pitch (floats) over cols: 32+4,  mult of 4 for float4

// Unordered tile pairs (ti <= tj) over 8 tiles of 32
__constant__ unsigned char cTI[NPAIR] = {0,0,0,0,0,0,0,0, 1,1,1,1,1,1,1, 2,2,2,2,2,2,
                                         3,3,3,3,3, 4,4,4,4, 5,5,5, 6,6, 7};
__constant__ unsigned char cTJ[NPAIR] = {0,1,2,3,4,5,6,7, 1,2,3,4,5,6,7, 2,3,4,5,6,7,
                                         3,4,5,6,7, 4,5,6,7, 5,6,7, 6,7, 7};

__global__ void zero_out_kernel(float* __restrict__ out) {
    out[threadIdx.x] = 0.0f;
}

// Packed f32x2 FMA (one FMA-pipe slot, 2 fp32 FMAs)
__device__ __forceinline__ float2 fma2(float2 a, float2 b, float2 c) {
    float2 d;
    asm("fma.rn.f32x2 %0, %1, %2, %3;"
        : "=l"(*reinterpret_cast<unsigned long long*>(&d))
        : "l"(*reinterpret_cast<const unsigned long long*>(&a)),
          "l"(*reinterpret_cast<const unsigned long long*>(&b)),
          "l"(*reinterpret_cast<const unsigned long long*>(&c)));
    return d;
}

// out[b] = sum_{i<j} (w0+w1)*w0*w1 * x[b,i]*x[b,j]
// Block = one unordered (i-tile, j-tile) pair x 128 batch rows.
// Diag tiles: strictly-upper A with full c (coalesced w, no double count).
// Thread tile: 4 rows x 4 j; register double-buffer hides LDS latency.
__global__ void __launch_bounds__(256, 2)
quad_kernel(const float* __restrict__ x, const float* __restrict__ w,
            float* __restrict__ out) {
    __shared__ __align__(16) float As [TT * TT];     // 4KB
    __shared__ __align__(16) float xIs[TT * XPI];    // [col i][row r], 16.9KB
    __shared__ __align__(16) float xJs[ROWS * XPJ];  // [row r][col j], 18.4KB

    const int t     = threadIdx.x;
    const int pair  = blockIdx.x;
    const int ibase = cTI[pair] * TT;
    const int jbase = cTJ[pair] * TT;
    const int rbase = blockIdx.y * ROWS;
    const bool diag = (ibase == jbase);

    // ---- A tile from w: all loads have gi<gj -> consecutive k -> coalesced.
#pragma unroll
    for (int step = 0; step < (TT * TT) / 256; ++step) {
        const int idx = step * 256 + t;
        const int gi = ibase + (idx >> 5);
        const int gj = jbase + (idx & 31);
        float cv = 0.0f;
        if (gj > gi) {
            const int k = gi * 255 - (gi * (gi - 1)) / 2 + (gj - gi - 1);
            const float w0 = __ldg(&w[k]);
            const float w1 = __ldg(&w[NI + k]);
            cv = (w0 + w1) * w0 * w1;
        }
        As[idx] = cv;
    }
    // ---- x tiles: warp reads 32 consecutive cols of one row (coalesced LDG).
#pragma unroll
    for (int step = 0; step < (ROWS * TT) / 256; ++step) {
        const int idx = step * 256 + t;
        const int c = idx & 31, r = idx >> 5;
        const float xv_i = __ldg(&x[(rbase + r) * DIM + ibase + c]);
        const float xv_j = diag ? xv_i : __ldg(&x[(rbase + r) * DIM + jbase + c]);
        xIs[c * XPI + r] = xv_i;     // transposed store (prologue only)
        xJs[r * XPJ + c] = xv_j;
    }
    __syncthreads();

    const int jg = t & 7;             // 8 j-groups x 4 j = 32 j
    const int j0 = jg * 4;
    const int r0 = (t >> 3) * 4;      // 32 row-groups x 4 rows = 128 rows

    float2 acc[4][2];                 // [row][j-pair]
#pragma unroll
    for (int rr = 0; rr < 4; ++rr) { acc[rr][0] = make_float2(0.f,0.f);
                                     acc[rr][1] = make_float2(0.f,0.f); }

    // Register double-buffered mainloop: prefetch i+1 while FMAing i.
    float4 xb[2], ab[2];
    xb[0] = *reinterpret_cast<const float4*>(&xIs[r0]);       // i = 0
    ab[0] = *reinterpret_cast<const float4*>(&As [j0]);
#pragma unroll
    for (int i = 0; i < TT; ++i) {
        const int cur = i & 1, nxt = cur ^ 1;
        if (i + 1 < TT) {
            xb[nxt] = *reinterpret_cast<const float4*>(&xIs[(i + 1) * XPI + r0]);
            ab[nxt] = *reinterpret_cast<const float4*>(&As [(i + 1) * TT  + j0]);
        }
        const float4 xr = xb[cur];
        const float4 av = ab[cur];
        const float2 A01 = make_float2(av.x, av.y);
        const float2 A23 = make_float2(av.z, av.w);
        const float xs[4] = {xr.x, xr.y, xr.z, xr.w};
#pragma unroll
        for (int rr = 0; rr < 4; ++rr) {
            const float2 xd = make_float2(xs[rr], xs[rr]);
            acc[rr][0] = fma2(xd, A01, acc[rr][0]);
            acc[rr][1] = fma2(xd, A23, acc[rr][1]);
        }
    }

    // ---- Epilogue: dot with x_J per row, shuffle-reduce the 8 j-groups.
    float v[4];
#pragma unroll
    for (int rr = 0; rr < 4; ++rr) {
        const float4 xj = *reinterpret_cast<const float4*>(&xJs[(r0 + rr) * XPJ + j0]);
        const float2 s  = fma2(acc[rr][0], make_float2(xj.x, xj.y),
                          fma2(acc[rr][1], make_float2(xj.z, xj.w), make_float2(0.f,0.f)));
        v[rr] = s.x + s.y;
    }
#pragma unroll
    for (int m = 4; m > 0; m >>= 1) {   // reduce within 8-lane j-groups
#pragma unroll
        for (int rr = 0; rr < 4; ++rr)
            v[rr] += __shfl_xor_sync(0xffffffffu, v[rr], m, 32);
    }
    if (jg == 0) {
#pragma unroll
        for (int rr = 0; rr < 4; ++rr)
            atomicAdd(&out[rbase + r0 + rr], v[rr]);
    }
}

extern "C" void kernel_launch(void* const* d_in, const int* in_sizes, int n_in,
                              void* d_out, int out_size) {
    const float* x = (const float*)d_in[0];
    const float* w = (const float*)d_in[1];
    float* out = (float*)d_out;

    zero_out_kernel<<<1, BATCH>>>(out);
    quad_kernel<<<dim3(NPAIR, BATCH / ROWS), 256>>>(x, w, out);  // 288 blocks, 2/SM
}